// round 8
// baseline (speedup 1.0000x reference)
#include <cuda_runtime.h>
#include <math.h>
#include <math_constants.h>
#include <cstdint>

#define BATCH 128
#define T     250
#define DIN   700
#define H     256
#define DOUT  20
#define MTOT  (BATCH*T)

// ---------------- scratch (static device globals; no dynamic alloc) ----------
__device__ float g_XW1[MTOT*H];
__device__ float g_S12[MTOT*H];
__device__ float g_W11t[H*H];
__device__ float g_W12t[H*H];
__device__ float g_W22t[H*H];
__device__ float g_Wot [H*DOUT];
__device__ __align__(16) float g_Whi[H*DIN];   // Wi1 tf32-split hi
__device__ __align__(16) float g_Wlo[H*DIN];   // Wi1 tf32-split lo

// ---------------- tf32 helpers ------------------------------------------------
__device__ __forceinline__ void split_tf32(float x, float& hi, float& lo) {
    uint32_t h; asm("cvt.rna.tf32.f32 %0, %1;" : "=r"(h) : "f"(x));
    hi = __uint_as_float(h);
    float r = x - hi;
    uint32_t l; asm("cvt.rna.tf32.f32 %0, %1;" : "=r"(l) : "f"(r));
    lo = __uint_as_float(l);
}
__device__ __forceinline__ void mma_tf32(float* d, const uint32_t* a, uint32_t b0, uint32_t b1) {
    asm volatile(
        "mma.sync.aligned.m16n8k8.row.col.f32.tf32.tf32.f32 "
        "{%0,%1,%2,%3}, {%4,%5,%6,%7}, {%8,%9}, {%0,%1,%2,%3};"
        : "+f"(d[0]), "+f"(d[1]), "+f"(d[2]), "+f"(d[3])
        : "r"(a[0]), "r"(a[1]), "r"(a[2]), "r"(a[3]), "r"(b0), "r"(b1));
}

// ---------------- transpose weights ------------------------------------------
__global__ void transpose_all(const float* __restrict__ W11, const float* __restrict__ W12,
                              const float* __restrict__ W22, const float* __restrict__ Wo)
{
    int idx = blockIdx.x * blockDim.x + threadIdx.x;
    if (idx < H*H) {
        int r = idx / H, c = idx % H;
        g_W11t[c*H + r] = W11[idx];
        g_W12t[c*H + r] = W12[idx];
        g_W22t[c*H + r] = W22[idx];
    }
    if (idx < DOUT*H) {
        int r = idx / H, c = idx % H;
        g_Wot[c*DOUT + r] = Wo[idx];
    }
}

// ---------------- pre-split Wi1 into tf32 hi/lo -------------------------------
__global__ void presplit_Wi1(const float* __restrict__ Wi1)
{
    int idx = blockIdx.x * blockDim.x + threadIdx.x;
    if (idx < H*DIN) {
        float hi, lo;
        split_tf32(Wi1[idx], hi, lo);
        g_Whi[idx] = hi;
        g_Wlo[idx] = lo;
    }
}

// smem: 4 tiles of 128 rows x 16 k-floats, row stride 20 floats (80 B)
#define RS    20
#define TSZF  (128*RS)
#define SM_TOTB (4*TSZF*4)        // 40960 bytes

// ---------------- Phase A: 3xTF32 mma.sync GEMM: XW1 = x@Wi1.T + b -----------
__global__ __launch_bounds__(256, 2)
void tf32_gemm_input(const float* __restrict__ A,
                     const float* __restrict__ bias1, const float* __restrict__ bias2)
{
    extern __shared__ float smf[];
    float* As_hi = smf;
    float* As_lo = smf + TSZF;
    float* Bs_hi = smf + 2*TSZF;
    float* Bs_lo = smf + 3*TSZF;

    int tid = threadIdx.x;
    int wid = tid >> 5, lane = tid & 31;
    int gid = lane >> 2, tig = lane & 3;
    int bm = blockIdx.x * 128, bn = blockIdx.y * 128;
    int wm = (wid >> 2) * 64;
    int wn = (wid & 3) * 32;

    float acc[4][4][4] = {};
    const int NCH = (DIN + 15) / 16;  // 44

    float4 pva[2], pwh[2], pwl[2];
    // preload chunk 0 (6 independent LDGs)
    #pragma unroll
    for (int i = 0; i < 2; ++i) {
        int f = tid + i*256, row = f >> 2, q = f & 3;
        int gk = q * 4;
        pva[i] = *(const float4*)(A    + (size_t)(bm + row)*DIN + gk);
        pwh[i] = *(const float4*)(g_Whi + (size_t)(bn + row)*DIN + gk);
        pwl[i] = *(const float4*)(g_Wlo + (size_t)(bn + row)*DIN + gk);
    }

    for (int ch = 0; ch < NCH; ++ch) {
        // ---- split + store staged regs ----
        #pragma unroll
        for (int i = 0; i < 2; ++i) {
            int f = tid + i*256, row = f >> 2, q = f & 3;
            float4 ah, al;
            split_tf32(pva[i].x, ah.x, al.x); split_tf32(pva[i].y, ah.y, al.y);
            split_tf32(pva[i].z, ah.z, al.z); split_tf32(pva[i].w, ah.w, al.w);
            int off = row*RS + q*4;
            *(float4*)(As_hi + off) = ah;
            *(float4*)(As_lo + off) = al;
            *(float4*)(Bs_hi + off) = pwh[i];
            *(float4*)(Bs_lo + off) = pwl[i];
        }
        __syncthreads();

        // ---- preload next chunk (hidden behind MMAs) ----
        if (ch + 1 < NCH) {
            int k0 = (ch + 1) * 16;
            #pragma unroll
            for (int i = 0; i < 2; ++i) {
                int f = tid + i*256, row = f >> 2, q = f & 3;
                int gk = k0 + q * 4;
                if (gk < DIN) {   // DIN%4==0 -> float4 all-valid or all-invalid
                    pva[i] = *(const float4*)(A    + (size_t)(bm + row)*DIN + gk);
                    pwh[i] = *(const float4*)(g_Whi + (size_t)(bn + row)*DIN + gk);
                    pwl[i] = *(const float4*)(g_Wlo + (size_t)(bn + row)*DIN + gk);
                } else {
                    pva[i] = make_float4(0.f,0.f,0.f,0.f);
                    pwh[i] = make_float4(0.f,0.f,0.f,0.f);
                    pwl[i] = make_float4(0.f,0.f,0.f,0.f);
                }
            }
        }

        // ---- 2 k-steps of 8 ----
        #pragma unroll
        for (int s = 0; s < 2; ++s) {
            int koff = s * 8 + tig;
            uint32_t ah[4][4], al[4][4];
            #pragma unroll
            for (int mt = 0; mt < 4; ++mt) {
                int r0 = wm + mt*16 + gid;
                const float* ph = As_hi + r0*RS + koff;
                const float* pl = As_lo + r0*RS + koff;
                ah[mt][0] = __float_as_uint(ph[0]);
                ah[mt][1] = __float_as_uint(ph[8*RS]);
                ah[mt][2] = __float_as_uint(ph[4]);
                ah[mt][3] = __float_as_uint(ph[8*RS+4]);
                al[mt][0] = __float_as_uint(pl[0]);
                al[mt][1] = __float_as_uint(pl[8*RS]);
                al[mt][2] = __float_as_uint(pl[4]);
                al[mt][3] = __float_as_uint(pl[8*RS+4]);
            }
            #pragma unroll
            for (int nt = 0; nt < 4; ++nt) {
                int nr = wn + nt*8 + gid;
                const float* qh = Bs_hi + nr*RS + koff;
                const float* ql = Bs_lo + nr*RS + koff;
                uint32_t bh0 = __float_as_uint(qh[0]);
                uint32_t bh1 = __float_as_uint(qh[4]);
                uint32_t bl0 = __float_as_uint(ql[0]);
                uint32_t bl1 = __float_as_uint(ql[4]);
                #pragma unroll
                for (int mt = 0; mt < 4; ++mt) {
                    mma_tf32(acc[mt][nt], ah[mt], bh0, bh1);
                    mma_tf32(acc[mt][nt], ah[mt], bl0, bl1);
                    mma_tf32(acc[mt][nt], al[mt], bh0, bh1);
                }
            }
        }
        __syncthreads();
    }

    // ---- epilogue ----
    #pragma unroll
    for (int nt = 0; nt < 4; ++nt) {
        int col = bn + wn + nt*8 + 2*tig;
        float b0 = bias1[col]   + bias2[col];
        float b1 = bias1[col+1] + bias2[col+1];
        #pragma unroll
        for (int mt = 0; mt < 4; ++mt) {
            int r0 = bm + wm + mt*16 + gid;
            float2 o0 = make_float2(acc[mt][nt][0] + b0, acc[mt][nt][1] + b1);
            float2 o1 = make_float2(acc[mt][nt][2] + b0, acc[mt][nt][3] + b1);
            *(float2*)&g_XW1[(size_t)r0*H + col]     = o0;
            *(float2*)&g_XW1[(size_t)(r0+8)*H + col] = o1;
        }
    }
}

// ---------------- layer-1 recurrence, 768 threads ----------------------------
// grp0 (tid<256):   neuron state + first-half gather + LIF + list build
// grp1 (256..511):  second-half gather -> hpart
// grp2 (512..767):  S12 row (step t-1) = sp1 @ W12.T + b12+b22, written to gmem
__global__ __launch_bounds__(768)
void recurrent1_kernel(const float* __restrict__ mem0,
                       const float* __restrict__ tau_adp, const float* __restrict__ tau_m,
                       const float* __restrict__ b12, const float* __restrict__ b22)
{
    int b = blockIdx.x;
    int tid = threadIdx.x;
    int j = tid & 255;
    int grp = tid >> 8;
    int wid = tid >> 5, lane = tid & 31;
    __shared__ int slist[2][H];
    __shared__ int scnt[2];
    __shared__ int wnp[8];
    __shared__ float hpart[H];

    float alpha = 0.f, ro = 0.f, mem = 0.f, bb = 0.01f, sp = 0.f, drv = 0.f, bs = 0.f;
    const float* dr = g_XW1 + (size_t)b*T*H + j;
    if (grp == 0) {
        alpha = (float)exp(-1.0 / (double)tau_m[j]);
        ro    = (float)exp(-1.0 / (double)tau_adp[j]);
        mem   = mem0[b*H + j];
        drv   = dr[0];
    } else if (grp == 2) {
        bs = b12[j] + b22[j];
    }
    if (tid == 0) scnt[0] = 0;
    __syncthreads();

    int cur = 0;
    for (int t = 0; t < T; ++t) {
        int c = scnt[cur];
        float hown = 0.f, drv_next = 0.f;
        if (grp == 0) {
            drv_next = (t+1 < T) ? dr[(size_t)(t+1)*H] : 0.f;
            int c0 = (c + 1) >> 1;
            float h0 = drv, h1 = 0.f, h2 = 0.f, h3 = 0.f;
            int k = 0;
            for (; k + 4 <= c0; k += 4) {
                int i0 = slist[cur][k], i1 = slist[cur][k+1];
                int i2 = slist[cur][k+2], i3 = slist[cur][k+3];
                h0 += g_W11t[i0*H + j];
                h1 += g_W11t[i1*H + j];
                h2 += g_W11t[i2*H + j];
                h3 += g_W11t[i3*H + j];
            }
            for (; k < c0; ++k) h0 += g_W11t[slist[cur][k]*H + j];
            hown = (h0 + h1) + (h2 + h3);
        } else if (grp == 1) {
            int c0 = (c + 1) >> 1;
            float h0 = 0.f, h1 = 0.f, h2 = 0.f, h3 = 0.f;
            int k = c0;
            for (; k + 4 <= c; k += 4) {
                int i0 = slist[cur][k], i1 = slist[cur][k+1];
                int i2 = slist[cur][k+2], i3 = slist[cur][k+3];
                h0 += g_W11t[i0*H + j];
                h1 += g_W11t[i1*H + j];
                h2 += g_W11t[i2*H + j];
                h3 += g_W11t[i3*H + j];
            }
            for (; k < c; ++k) h0 += g_W11t[slist[cur][k]*H + j];
            hpart[j] = (h0 + h1) + (h2 + h3);
        } else {
            if (t > 0) {
                float h0 = bs, h1 = 0.f, h2 = 0.f, h3 = 0.f;
                int k = 0;
                for (; k + 4 <= c; k += 4) {
                    int i0 = slist[cur][k], i1 = slist[cur][k+1];
                    int i2 = slist[cur][k+2], i3 = slist[cur][k+3];
                    h0 += g_W12t[i0*H + j];
                    h1 += g_W12t[i1*H + j];
                    h2 += g_W12t[i2*H + j];
                    h3 += g_W12t[i3*H + j];
                }
                for (; k < c; ++k) h0 += g_W12t[slist[cur][k]*H + j];
                g_S12[((size_t)b*T + (t-1))*H + j] = (h0 + h1) + (h2 + h3);
            }
        }
        __syncthreads();                       // A: hpart ready

        unsigned bal = 0u;
        if (grp == 0) {
            float h = hown + hpart[j];
            bb = ro*bb + (1.f - ro)*sp;
            float Bt = 0.01f + 1.8f*bb;
            mem = mem*alpha + (1.f - alpha)*h - Bt*sp;
            sp  = (mem - Bt > 0.f) ? 1.f : 0.f;
            bal = __ballot_sync(0xFFFFFFFFu, sp != 0.f);
            if (lane == 0) wnp[wid] = __popc(bal);
            drv = drv_next;
        }
        __syncthreads();                       // B: wnp ready

        int nxt = cur ^ 1;
        if (grp == 0) {
            int base = 0, total = 0;
            #pragma unroll
            for (int w = 0; w < 8; ++w) {
                int v = wnp[w];
                total += v;
                if (w < wid) base += v;
            }
            if (sp != 0.f) {
                int pos = base + __popc(bal & ((1u << lane) - 1u));
                slist[nxt][pos] = j;
            }
            if (tid == 0) scnt[nxt] = total;
        }
        __syncthreads();                       // C: slist[nxt] ready
        cur = nxt;
    }

    // epilogue: S12 row T-1 from final spike list
    if (grp == 2) {
        int c = scnt[cur];
        float h0 = bs, h1 = 0.f, h2 = 0.f, h3 = 0.f;
        int k = 0;
        for (; k + 4 <= c; k += 4) {
            int i0 = slist[cur][k], i1 = slist[cur][k+1];
            int i2 = slist[cur][k+2], i3 = slist[cur][k+3];
            h0 += g_W12t[i0*H + j];
            h1 += g_W12t[i1*H + j];
            h2 += g_W12t[i2*H + j];
            h3 += g_W12t[i3*H + j];
        }
        for (; k < c; ++k) h0 += g_W12t[slist[cur][k]*H + j];
        g_S12[((size_t)b*T + (T-1))*H + j] = (h0 + h1) + (h2 + h3);
    }
}

// ---------------- layer-2 recurrence, 544 threads ----------------------------
// grp0 (tid<256): neurons (first-half gather); grp1 (256..511): second-half
// gather; warp 16 (512..543): Wo list-GEMM + memo + softmax accumulation.
__global__ __launch_bounds__(544)
void recurrent2_fused(const float* __restrict__ mem0,
                      const float* __restrict__ tau_adp, const float* __restrict__ tau_m,
                      const float* __restrict__ memo0, const float* __restrict__ tau_m_o,
                      const float* __restrict__ bo, float* __restrict__ outp)
{
    int b   = blockIdx.x;
    int tid = threadIdx.x;
    int j   = tid & 255;
    int wid = tid >> 5, lane = tid & 31;
    int grp = (tid < 256) ? 0 : (tid < 512 ? 1 : 2);
    __shared__ int slist[2][H];
    __shared__ int scnt[2];
    __shared__ int wnp[8];
    __shared__ float hpart[H];

    float alpha = 0.f, ro = 0.f, mem = 0.f, bb = 0.01f, sp = 0.f, drv = 0.f;
    const float* dr = g_S12 + (size_t)b*T*H + j;
    float alpha_o = 0.f, memo = 0.f, acc = 0.f, bol = 0.f;
    bool act = false;

    if (grp == 0) {
        alpha = (float)exp(-1.0 / (double)tau_m[j]);
        ro    = (float)exp(-1.0 / (double)tau_adp[j]);
        mem   = mem0[b*H + j];
        drv   = dr[0];
    } else if (grp == 2) {
        act = lane < DOUT;
        int l = act ? lane : 0;
        alpha_o = (float)exp(-1.0 / (double)tau_m_o[l]);
        memo    = memo0[b*DOUT + l];
        bol     = bo[l];
    }
    if (tid == 0) scnt[0] = 0;
    __syncthreads();

    int cur = 0;
    for (int t = 0; t < T; ++t) {
        int c = scnt[cur];
        float hown = 0.f, drv_next = 0.f;
        if (grp == 0) {
            drv_next = (t+1 < T) ? dr[(size_t)(t+1)*H] : 0.f;
            int c0 = (c + 1) >> 1;
            float h0 = drv, h1 = 0.f, h2 = 0.f, h3 = 0.f;
            int k = 0;
            for (; k + 4 <= c0; k += 4) {
                int i0 = slist[cur][k], i1 = slist[cur][k+1];
                int i2 = slist[cur][k+2], i3 = slist[cur][k+3];
                h0 += g_W22t[i0*H + j];
                h1 += g_W22t[i1*H + j];
                h2 += g_W22t[i2*H + j];
                h3 += g_W22t[i3*H + j];
            }
            for (; k < c0; ++k) h0 += g_W22t[slist[cur][k]*H + j];
            hown = (h0 + h1) + (h2 + h3);
        } else if (grp == 1) {
            int c0 = (c + 1) >> 1;
            float h0 = 0.f, h1 = 0.f, h2 = 0.f, h3 = 0.f;
            int k = c0;
            for (; k + 4 <= c; k += 4) {
                int i0 = slist[cur][k], i1 = slist[cur][k+1];
                int i2 = slist[cur][k+2], i3 = slist[cur][k+3];
                h0 += g_W22t[i0*H + j];
                h1 += g_W22t[i1*H + j];
                h2 += g_W22t[i2*H + j];
                h3 += g_W22t[i3*H + j];
            }
            for (; k < c; ++k) h0 += g_W22t[slist[cur][k]*H + j];
            hpart[j] = (h0 + h1) + (h2 + h3);
        } else if (t > 0) {
            // output warp: consume sp2 of step t-1
            int l = act ? lane : 0;
            float o0 = bol, o1 = 0.f;
            int k = 0;
            for (; k + 2 <= c; k += 2) {
                int i0 = slist[cur][k], i1 = slist[cur][k+1];
                o0 += g_Wot[i0*DOUT + l];
                o1 += g_Wot[i1*DOUT + l];
            }
            for (; k < c; ++k) o0 += g_Wot[slist[cur][k]*DOUT + l];
            memo = memo*alpha_o + (1.f - alpha_o)*(o0 + o1);
            float v = act ? memo : -CUDART_INF_F;
            #pragma unroll
            for (int off = 16; off; off >>= 1)
                v = fmaxf(v, __shfl_xor_sync(0xFFFFFFFFu, v, off));
            float e = act ? expf(memo - v) : 0.f;
            float s = e;
            #pragma unroll
            for (int off = 16; off; off >>= 1)
                s += __shfl_xor_sync(0xFFFFFFFFu, s, off);
            if (t - 1 > 10) acc += e / s;
        }
        __syncthreads();                       // A

        unsigned bal = 0u;
        if (grp == 0) {
            float h = hown + hpart[j];
            bb = ro*bb + (1.f - ro)*sp;
            float Bt = 0.01f + 1.8f*bb;
            mem = mem*alpha + (1.f - alpha)*h - Bt*sp;
            sp  = (mem - Bt > 0.f) ? 1.f : 0.f;
            bal = __ballot_sync(0xFFFFFFFFu, sp != 0.f);
            if (lane == 0) wnp[wid] = __popc(bal);
            drv = drv_next;
        }
        __syncthreads();                       // B

        int nxt = cur ^ 1;
        if (grp == 0) {
            int base = 0, total = 0;
            #pragma unroll
            for (int w = 0; w < 8; ++w) {
                int v = wnp[w];
                total += v;
                if (w < wid) base += v;
            }
            if (sp != 0.f) {
                int pos = base + __popc(bal & ((1u << lane) - 1u));
                slist[nxt][pos] = j;
            }
            if (tid == 0) scnt[nxt] = total;
        }
        __syncthreads();                       // C
        cur = nxt;
    }

    // epilogue: output warp processes final step T-1
    if (grp == 2) {
        int c = scnt[cur];
        int l = act ? lane : 0;
        float o0 = bol, o1 = 0.f;
        int k = 0;
        for (; k + 2 <= c; k += 2) {
            int i0 = slist[cur][k], i1 = slist[cur][k+1];
            o0 += g_Wot[i0*DOUT + l];
            o1 += g_Wot[i1*DOUT + l];
        }
        for (; k < c; ++k) o0 += g_Wot[slist[cur][k]*DOUT + l];
        memo = memo*alpha_o + (1.f - alpha_o)*(o0 + o1);
        float v = act ? memo : -CUDART_INF_F;
        #pragma unroll
        for (int off = 16; off; off >>= 1)
            v = fmaxf(v, __shfl_xor_sync(0xFFFFFFFFu, v, off));
        float e = act ? expf(memo - v) : 0.f;
        float s = e;
        #pragma unroll
        for (int off = 16; off; off >>= 1)
            s += __shfl_xor_sync(0xFFFFFFFFu, s, off);
        acc += e / s;
        if (act) outp[b*DOUT + lane] = acc;
    }
}

// ---------------- launch ------------------------------------------------------
extern "C" void kernel_launch(void* const* d_in, const int* in_sizes, int n_in,
                              void* d_out, int out_size)
{
    const float* x        = (const float*)d_in[0];
    const float* mem1_0   = (const float*)d_in[1];
    const float* mem2_0   = (const float*)d_in[2];
    const float* memo_0   = (const float*)d_in[3];
    const float* Wi1      = (const float*)d_in[4];
    const float* bi1      = (const float*)d_in[5];
    const float* W11      = (const float*)d_in[6];
    const float* b11      = (const float*)d_in[7];
    const float* W12      = (const float*)d_in[8];
    const float* b12      = (const float*)d_in[9];
    const float* W22      = (const float*)d_in[10];
    const float* b22      = (const float*)d_in[11];
    const float* Wo       = (const float*)d_in[12];
    const float* bo       = (const float*)d_in[13];
    const float* tau_adp1 = (const float*)d_in[14];
    const float* tau_adp2 = (const float*)d_in[15];
    const float* tau_m1   = (const float*)d_in[16];
    const float* tau_m2   = (const float*)d_in[17];
    const float* tau_mo   = (const float*)d_in[18];
    float* outp = (float*)d_out;

    cudaFuncSetAttribute(tf32_gemm_input, cudaFuncAttributeMaxDynamicSharedMemorySize, SM_TOTB);

    // 1) transpose weights
    transpose_all<<<(H*H + 255)/256, 256>>>(W11, W12, W22, Wo);

    // 2) pre-split Wi1 into tf32 hi/lo
    presplit_Wi1<<<(H*DIN + 255)/256, 256>>>(Wi1);

    // 3) XW1 = x @ Wi1.T + bi1 + b11   (3xTF32 mma.sync GEMM, reg-prefetched)
    dim3 gA(MTOT/128, H/128);
    tf32_gemm_input<<<gA, 256, SM_TOTB>>>(x, bi1, b11);

    // 4) layer-1 recurrence + fused S12 list-GEMM  <-- profiled slot
    recurrent1_kernel<<<BATCH, 768>>>(mem1_0, tau_adp1, tau_m1, b12, b22);

    // 5) layer-2 recurrence + fused Wo list-GEMM + memo/softmax accumulation
    recurrent2_fused<<<BATCH, 544>>>(mem2_0, tau_adp2, tau_m2, memo_0, tau_mo, bo, outp);
}

// round 9
// speedup vs baseline: 1.0492x; 1.0492x over previous
#include <cuda_runtime.h>
#include <math.h>
#include <math_constants.h>
#include <cstdint>

#define BATCH 128
#define T     250
#define DIN   700
#define H     256
#define DOUT  20
#define MTOT  (BATCH*T)
#define LSTR  256

// ---------------- scratch (static device globals; no dynamic alloc) ----------
__device__ float g_XW1[MTOT*H];
__device__ float g_S12[MTOT*H];
__device__ __align__(16) int g_list1[MTOT*LSTR];
__device__ int   g_cnt1 [MTOT];
__device__ float g_W11t[H*H];
__device__ float g_W12t[H*H];
__device__ float g_W22t[H*H];
__device__ float g_Wot [H*DOUT];
__device__ __align__(16) float g_Whi[H*DIN];
__device__ __align__(16) float g_Wlo[H*DIN];

// ---------------- tf32 helpers ------------------------------------------------
__device__ __forceinline__ void split_tf32(float x, float& hi, float& lo) {
    uint32_t h; asm("cvt.rna.tf32.f32 %0, %1;" : "=r"(h) : "f"(x));
    hi = __uint_as_float(h);
    float r = x - hi;
    uint32_t l; asm("cvt.rna.tf32.f32 %0, %1;" : "=r"(l) : "f"(r));
    lo = __uint_as_float(l);
}
__device__ __forceinline__ void mma_tf32(float* d, const uint32_t* a, uint32_t b0, uint32_t b1) {
    asm volatile(
        "mma.sync.aligned.m16n8k8.row.col.f32.tf32.tf32.f32 "
        "{%0,%1,%2,%3}, {%4,%5,%6,%7}, {%8,%9}, {%0,%1,%2,%3};"
        : "+f"(d[0]), "+f"(d[1]), "+f"(d[2]), "+f"(d[3])
        : "r"(a[0]), "r"(a[1]), "r"(a[2]), "r"(a[3]), "r"(b0), "r"(b1));
}

// ---------------- transpose weights ------------------------------------------
__global__ void transpose_all(const float* __restrict__ W11, const float* __restrict__ W12,
                              const float* __restrict__ W22, const float* __restrict__ Wo)
{
    int idx = blockIdx.x * blockDim.x + threadIdx.x;
    if (idx < H*H) {
        int r = idx / H, c = idx % H;
        g_W11t[c*H + r] = W11[idx];
        g_W12t[c*H + r] = W12[idx];
        g_W22t[c*H + r] = W22[idx];
    }
    if (idx < DOUT*H) {
        int r = idx / H, c = idx % H;
        g_Wot[c*DOUT + r] = Wo[idx];
    }
}

// ---------------- pre-split Wi1 into tf32 hi/lo -------------------------------
__global__ void presplit_Wi1(const float* __restrict__ Wi1)
{
    int idx = blockIdx.x * blockDim.x + threadIdx.x;
    if (idx < H*DIN) {
        float hi, lo;
        split_tf32(Wi1[idx], hi, lo);
        g_Whi[idx] = hi;
        g_Wlo[idx] = lo;
    }
}

// smem: 4 tiles of 128 rows x 16 k-floats, row stride 20 floats (80 B)
#define RS    20
#define TSZF  (128*RS)
#define SM_TOTB (4*TSZF*4)        // 40960 bytes

// ---------------- Phase A: 3xTF32 mma.sync GEMM: XW1 = x@Wi1.T + b -----------
__global__ __launch_bounds__(256, 2)
void tf32_gemm_input(const float* __restrict__ A,
                     const float* __restrict__ bias1, const float* __restrict__ bias2)
{
    extern __shared__ float smf[];
    float* As_hi = smf;
    float* As_lo = smf + TSZF;
    float* Bs_hi = smf + 2*TSZF;
    float* Bs_lo = smf + 3*TSZF;

    int tid = threadIdx.x;
    int wid = tid >> 5, lane = tid & 31;
    int gid = lane >> 2, tig = lane & 3;
    int bm = blockIdx.x * 128, bn = blockIdx.y * 128;
    int wm = (wid >> 2) * 64;
    int wn = (wid & 3) * 32;

    float acc[4][4][4] = {};
    const int NCH = (DIN + 15) / 16;  // 44

    float4 pva[2], pwh[2], pwl[2];
    #pragma unroll
    for (int i = 0; i < 2; ++i) {
        int f = tid + i*256, row = f >> 2, q = f & 3;
        int gk = q * 4;
        pva[i] = *(const float4*)(A     + (size_t)(bm + row)*DIN + gk);
        pwh[i] = *(const float4*)(g_Whi + (size_t)(bn + row)*DIN + gk);
        pwl[i] = *(const float4*)(g_Wlo + (size_t)(bn + row)*DIN + gk);
    }

    for (int ch = 0; ch < NCH; ++ch) {
        #pragma unroll
        for (int i = 0; i < 2; ++i) {
            int f = tid + i*256, row = f >> 2, q = f & 3;
            float4 ah, al;
            split_tf32(pva[i].x, ah.x, al.x); split_tf32(pva[i].y, ah.y, al.y);
            split_tf32(pva[i].z, ah.z, al.z); split_tf32(pva[i].w, ah.w, al.w);
            int off = row*RS + q*4;
            *(float4*)(As_hi + off) = ah;
            *(float4*)(As_lo + off) = al;
            *(float4*)(Bs_hi + off) = pwh[i];
            *(float4*)(Bs_lo + off) = pwl[i];
        }
        __syncthreads();

        if (ch + 1 < NCH) {
            int k0 = (ch + 1) * 16;
            #pragma unroll
            for (int i = 0; i < 2; ++i) {
                int f = tid + i*256, row = f >> 2, q = f & 3;
                int gk = k0 + q * 4;
                if (gk < DIN) {
                    pva[i] = *(const float4*)(A     + (size_t)(bm + row)*DIN + gk);
                    pwh[i] = *(const float4*)(g_Whi + (size_t)(bn + row)*DIN + gk);
                    pwl[i] = *(const float4*)(g_Wlo + (size_t)(bn + row)*DIN + gk);
                } else {
                    pva[i] = make_float4(0.f,0.f,0.f,0.f);
                    pwh[i] = make_float4(0.f,0.f,0.f,0.f);
                    pwl[i] = make_float4(0.f,0.f,0.f,0.f);
                }
            }
        }

        #pragma unroll
        for (int s = 0; s < 2; ++s) {
            int koff = s * 8 + tig;
            uint32_t ah[4][4], al[4][4];
            #pragma unroll
            for (int mt = 0; mt < 4; ++mt) {
                int r0 = wm + mt*16 + gid;
                const float* ph = As_hi + r0*RS + koff;
                const float* pl = As_lo + r0*RS + koff;
                ah[mt][0] = __float_as_uint(ph[0]);
                ah[mt][1] = __float_as_uint(ph[8*RS]);
                ah[mt][2] = __float_as_uint(ph[4]);
                ah[mt][3] = __float_as_uint(ph[8*RS+4]);
                al[mt][0] = __float_as_uint(pl[0]);
                al[mt][1] = __float_as_uint(pl[8*RS]);
                al[mt][2] = __float_as_uint(pl[4]);
                al[mt][3] = __float_as_uint(pl[8*RS+4]);
            }
            #pragma unroll
            for (int nt = 0; nt < 4; ++nt) {
                int nr = wn + nt*8 + gid;
                const float* qh = Bs_hi + nr*RS + koff;
                const float* ql = Bs_lo + nr*RS + koff;
                uint32_t bh0 = __float_as_uint(qh[0]);
                uint32_t bh1 = __float_as_uint(qh[4]);
                uint32_t bl0 = __float_as_uint(ql[0]);
                uint32_t bl1 = __float_as_uint(ql[4]);
                #pragma unroll
                for (int mt = 0; mt < 4; ++mt) {
                    mma_tf32(acc[mt][nt], ah[mt], bh0, bh1);
                    mma_tf32(acc[mt][nt], ah[mt], bl0, bl1);
                    mma_tf32(acc[mt][nt], al[mt], bh0, bh1);
                }
            }
        }
        __syncthreads();
    }

    // epilogue: streaming stores (do not pollute L1/L2 for rec1's weights)
    #pragma unroll
    for (int nt = 0; nt < 4; ++nt) {
        int col = bn + wn + nt*8 + 2*tig;
        float b0 = bias1[col]   + bias2[col];
        float b1 = bias1[col+1] + bias2[col+1];
        #pragma unroll
        for (int mt = 0; mt < 4; ++mt) {
            int r0 = bm + wm + mt*16 + gid;
            float2 o0 = make_float2(acc[mt][nt][0] + b0, acc[mt][nt][1] + b1);
            float2 o1 = make_float2(acc[mt][nt][2] + b0, acc[mt][nt][3] + b1);
            __stcs((float2*)&g_XW1[(size_t)r0*H + col],     o0);
            __stcs((float2*)&g_XW1[(size_t)(r0+8)*H + col], o1);
        }
    }
}

// ---------------- layer-1 recurrence: index-list step loop (256 thr) ---------
__global__ __launch_bounds__(H)
void recurrent1_kernel(const float* __restrict__ mem0,
                       const float* __restrict__ tau_adp, const float* __restrict__ tau_m)
{
    int b = blockIdx.x;
    int j = threadIdx.x;
    int wid = j >> 5, lane = j & 31;
    __shared__ __align__(16) int slist[2][H];
    __shared__ int scnt[2];
    __shared__ __align__(16) int wnp[8];

    float alpha = (float)exp(-1.0 / (double)tau_m[j]);
    float ro    = (float)exp(-1.0 / (double)tau_adp[j]);
    float mem   = mem0[b*H + j];
    float bb    = 0.01f;
    float sp    = 0.f;

    if (j == 0) scnt[0] = 0;
    __syncthreads();

    const float* dr = g_XW1 + (size_t)b*T*H + j;
    float drv = __ldcs(dr);
    int cur = 0;
    for (int t = 0; t < T; ++t) {
        float drv_next = (t+1 < T) ? __ldcs(dr + (size_t)(t+1)*H) : 0.f;
        int c = scnt[cur];
        float h0 = drv, h1 = 0.f, h2 = 0.f, h3 = 0.f;
        int k = 0;
        for (; k + 4 <= c; k += 4) {
            int4 iv = *(const int4*)&slist[cur][k];
            h0 += g_W11t[iv.x*H + j];
            h1 += g_W11t[iv.y*H + j];
            h2 += g_W11t[iv.z*H + j];
            h3 += g_W11t[iv.w*H + j];
        }
        for (; k < c; ++k) h0 += g_W11t[slist[cur][k]*H + j];
        float h = (h0 + h1) + (h2 + h3);

        bb = ro*bb + (1.f - ro)*sp;
        float Bt = 0.01f + 1.8f*bb;
        mem = mem*alpha + (1.f - alpha)*h - Bt*sp;
        sp  = (mem - Bt > 0.f) ? 1.f : 0.f;

        unsigned bal = __ballot_sync(0xFFFFFFFFu, sp != 0.f);
        if (lane == 0) wnp[wid] = __popc(bal);
        __syncthreads();

        int nxt = cur ^ 1;
        int4 w0 = *(const int4*)&wnp[0];
        int4 w1 = *(const int4*)&wnp[4];
        int cnt8[8] = {w0.x,w0.y,w0.z,w0.w,w1.x,w1.y,w1.z,w1.w};
        int base = 0, total = 0;
        #pragma unroll
        for (int w = 0; w < 8; ++w) {
            total += cnt8[w];
            if (w < wid) base += cnt8[w];
        }
        size_t rowidx = (size_t)b*T + t;
        if (sp != 0.f) {
            int pos = base + __popc(bal & ((1u << lane) - 1u));
            slist[nxt][pos] = j;
            __stcs(&g_list1[rowidx*LSTR + pos], j);
        }
        if (j == 0) {
            scnt[nxt] = total;
            __stcs(&g_cnt1[rowidx], total);
        }
        __syncthreads();
        cur = nxt;
        drv = drv_next;
    }
}

// ---------------- list-GEMM: S12 = sp1 @ W12.T + b12 + b22 -------------------
__global__ __launch_bounds__(H)
void bitgemm256_kernel(const float* __restrict__ bias1, const float* __restrict__ bias2)
{
    __shared__ __align__(16) int slist[8][LSTR];
    __shared__ int scnt[8];
    int j = threadIdx.x;
    int wid = j >> 5, lane = j & 31;
    int r0 = blockIdx.x * 8;

    {
        size_t row = (size_t)(r0 + wid);
        int c = g_cnt1[row];
        for (int k = lane; k < c; k += 32)
            slist[wid][k] = g_list1[row*LSTR + k];
        if (lane == 0) scnt[wid] = c;
    }
    __syncthreads();

    float bs = bias1[j] + bias2[j];
    #pragma unroll 1
    for (int r = 0; r < 8; ++r) {
        int c = scnt[r];
        float h0 = bs, h1 = 0.f, h2 = 0.f, h3 = 0.f;
        int k = 0;
        for (; k + 4 <= c; k += 4) {
            int4 iv = *(const int4*)&slist[r][k];
            h0 += g_W12t[iv.x*H + j];
            h1 += g_W12t[iv.y*H + j];
            h2 += g_W12t[iv.z*H + j];
            h3 += g_W12t[iv.w*H + j];
        }
        for (; k < c; ++k) h0 += g_W12t[slist[r][k]*H + j];
        __stcs(&g_S12[(size_t)(r0 + r)*H + j], (h0 + h1) + (h2 + h3));
    }
}

// ---------------- layer-2 recurrence FUSED with Wo list-GEMM + output --------
// 288 threads: warps 0-7 = 256 neurons; warp 8 = output warp (one step behind).
__global__ __launch_bounds__(288)
void recurrent2_fused(const float* __restrict__ mem0,
                      const float* __restrict__ tau_adp, const float* __restrict__ tau_m,
                      const float* __restrict__ memo0, const float* __restrict__ tau_m_o,
                      const float* __restrict__ bo, float* __restrict__ outp)
{
    int b   = blockIdx.x;
    int tid = threadIdx.x;
    int wid = tid >> 5, lane = tid & 31;
    __shared__ __align__(16) int slist[2][H];
    __shared__ int scnt[2];
    __shared__ __align__(16) int wnp[8];

    float alpha = 0.f, ro = 0.f, mem = 0.f, bb = 0.01f, sp = 0.f;
    const float* dr = g_S12 + (size_t)b*T*H + tid;
    float drv = 0.f;
    float alpha_o = 0.f, memo = 0.f, acc = 0.f, bol = 0.f;
    bool act = false;

    if (tid < H) {
        alpha = (float)exp(-1.0 / (double)tau_m[tid]);
        ro    = (float)exp(-1.0 / (double)tau_adp[tid]);
        mem   = mem0[b*H + tid];
        drv   = __ldcs(dr);
    } else {
        act = lane < DOUT;
        int l = act ? lane : 0;
        alpha_o = (float)exp(-1.0 / (double)tau_m_o[l]);
        memo    = memo0[b*DOUT + l];
        bol     = bo[l];
    }

    if (tid == 0) scnt[0] = 0;
    __syncthreads();

    int cur = 0;
    for (int t = 0; t < T; ++t) {
        unsigned bal = 0u;
        if (tid < H) {
            float drv_next = (t+1 < T) ? __ldcs(dr + (size_t)(t+1)*H) : 0.f;
            int c = scnt[cur];
            float h0 = drv, h1 = 0.f, h2 = 0.f, h3 = 0.f;
            int k = 0;
            for (; k + 4 <= c; k += 4) {
                int4 iv = *(const int4*)&slist[cur][k];
                h0 += g_W22t[iv.x*H + tid];
                h1 += g_W22t[iv.y*H + tid];
                h2 += g_W22t[iv.z*H + tid];
                h3 += g_W22t[iv.w*H + tid];
            }
            for (; k < c; ++k) h0 += g_W22t[slist[cur][k]*H + tid];
            float h = (h0 + h1) + (h2 + h3);

            bb = ro*bb + (1.f - ro)*sp;
            float Bt = 0.01f + 1.8f*bb;
            mem = mem*alpha + (1.f - alpha)*h - Bt*sp;
            sp  = (mem - Bt > 0.f) ? 1.f : 0.f;

            bal = __ballot_sync(0xFFFFFFFFu, sp != 0.f);
            if (lane == 0) wnp[wid] = __popc(bal);
            drv = drv_next;
        } else if (t > 0) {
            int c = scnt[cur];
            int l = act ? lane : 0;
            float o0 = bol, o1 = 0.f;
            int k = 0;
            for (; k + 2 <= c; k += 2) {
                int i0 = slist[cur][k], i1 = slist[cur][k+1];
                o0 += g_Wot[i0*DOUT + l];
                o1 += g_Wot[i1*DOUT + l];
            }
            for (; k < c; ++k) o0 += g_Wot[slist[cur][k]*DOUT + l];
            memo = memo*alpha_o + (1.f - alpha_o)*(o0 + o1);
            float v = act ? memo : -CUDART_INF_F;
            #pragma unroll
            for (int off = 16; off; off >>= 1)
                v = fmaxf(v, __shfl_xor_sync(0xFFFFFFFFu, v, off));
            float e = act ? expf(memo - v) : 0.f;
            float s = e;
            #pragma unroll
            for (int off = 16; off; off >>= 1)
                s += __shfl_xor_sync(0xFFFFFFFFu, s, off);
            if (t - 1 > 10) acc += e / s;
        }
        __syncthreads();

        int nxt = cur ^ 1;
        if (tid < H) {
            int4 w0 = *(const int4*)&wnp[0];
            int4 w1 = *(const int4*)&wnp[4];
            int cnt8[8] = {w0.x,w0.y,w0.z,w0.w,w1.x,w1.y,w1.z,w1.w};
            int base = 0, total = 0;
            #pragma unroll
            for (int w = 0; w < 8; ++w) {
                total += cnt8[w];
                if (w < wid) base += cnt8[w];
            }
            if (sp != 0.f) {
                int pos = base + __popc(bal & ((1u << lane) - 1u));
                slist[nxt][pos] = tid;
            }
            if (tid == 0) scnt[nxt] = total;
        }
        __syncthreads();
        cur = nxt;
    }

    if (tid >= H) {
        int c = scnt[cur];
        int l = act ? lane : 0;
        float o0 = bol, o1 = 0.f;
        int k = 0;
        for (; k + 2 <= c; k += 2) {
            int i0 = slist[cur][k], i1 = slist[cur][k+1];
            o0 += g_Wot[i0*DOUT + l];
            o1 += g_Wot[i1*DOUT + l];
        }
        for (; k < c; ++k) o0 += g_Wot[slist[cur][k]*DOUT + l];
        memo = memo*alpha_o + (1.f - alpha_o)*(o0 + o1);
        float v = act ? memo : -CUDART_INF_F;
        #pragma unroll
        for (int off = 16; off; off >>= 1)
            v = fmaxf(v, __shfl_xor_sync(0xFFFFFFFFu, v, off));
        float e = act ? expf(memo - v) : 0.f;
        float s = e;
        #pragma unroll
        for (int off = 16; off; off >>= 1)
            s += __shfl_xor_sync(0xFFFFFFFFu, s, off);
        acc += e / s;
        if (act) outp[b*DOUT + lane] = acc;
    }
}

// ---------------- launch ------------------------------------------------------
extern "C" void kernel_launch(void* const* d_in, const int* in_sizes, int n_in,
                              void* d_out, int out_size)
{
    const float* x        = (const float*)d_in[0];
    const float* mem1_0   = (const float*)d_in[1];
    const float* mem2_0   = (const float*)d_in[2];
    const float* memo_0   = (const float*)d_in[3];
    const float* Wi1      = (const float*)d_in[4];
    const float* bi1      = (const float*)d_in[5];
    const float* W11      = (const float*)d_in[6];
    const float* b11      = (const float*)d_in[7];
    const float* W12      = (const float*)d_in[8];
    const float* b12      = (const float*)d_in[9];
    const float* W22      = (const float*)d_in[10];
    const float* b22      = (const float*)d_in[11];
    const float* Wo       = (const float*)d_in[12];
    const float* bo       = (const float*)d_in[13];
    const float* tau_adp1 = (const float*)d_in[14];
    const float* tau_adp2 = (const float*)d_in[15];
    const float* tau_m1   = (const float*)d_in[16];
    const float* tau_m2   = (const float*)d_in[17];
    const float* tau_mo   = (const float*)d_in[18];
    float* outp = (float*)d_out;

    cudaFuncSetAttribute(tf32_gemm_input, cudaFuncAttributeMaxDynamicSharedMemorySize, SM_TOTB);

    // 1) transpose weights
    transpose_all<<<(H*H + 255)/256, 256>>>(W11, W12, W22, Wo);

    // 2) pre-split Wi1 into tf32 hi/lo
    presplit_Wi1<<<(H*DIN + 255)/256, 256>>>(Wi1);

    // 3) XW1 = x @ Wi1.T + bi1 + b11
    dim3 gA(MTOT/128, H/128);
    tf32_gemm_input<<<gA, 256, SM_TOTB>>>(x, bi1, b11);

    // 4) layer-1 recurrence -> spike index lists   <-- profiled slot
    recurrent1_kernel<<<BATCH, H>>>(mem1_0, tau_adp1, tau_m1);

    // 5) S12 = sp1 @ W12.T + b12 + b22
    bitgemm256_kernel<<<MTOT/8, H>>>(b12, b22);

    // 6) layer-2 recurrence + fused Wo list-GEMM + memo/softmax accumulation
    recurrent2_fused<<<BATCH, 288>>>(mem2_0, tau_adp2, tau_m2, memo_0, tau_mo, bo, outp);
}